// round 1
// baseline (speedup 1.0000x reference)
#include <cuda_runtime.h>
#include <math.h>

// Problem dims (fixed by the dataset)
#define S_  512
#define B_  64
#define IN_ 512
#define H_  1024
#define OUT_ 512
#define MB_ (S_ * B_)          // 32768 rows for all time-parallel GEMMs

// ---------------------------------------------------------------------------
// Scratch (no cudaMalloc allowed): 4 buffers of S*B*H floats = 4 * 134 MB
// ---------------------------------------------------------------------------
__device__ float g_xa[(size_t)S_ * B_ * H_];
__device__ float g_xc[(size_t)S_ * B_ * H_];
__device__ float g_xh[(size_t)S_ * B_ * H_];
__device__ float g_y [(size_t)S_ * B_ * H_];

// ---------------------------------------------------------------------------
// SGEMM: C[M,N] = A[M,K] @ B[K,N] + bias[N]
// 128x128 block tile, K-tile 8, 256 threads, 8x8 register tile per thread.
// All dims here are multiples of the tiles (M=32768, N in {512,1024},
// K in {512,1024}) so no boundary guards.
// ---------------------------------------------------------------------------
__global__ __launch_bounds__(256, 2)
void sgemm_bias(const float* __restrict__ A, const float* __restrict__ B,
                const float* __restrict__ bias, float* __restrict__ C,
                int M, int N, int K)
{
    const int BM = 128, BN = 128, BK = 8, TM = 8, TN = 8;
    __shared__ float As[BK][BM];
    __shared__ float Bs[BK][BN];

    const int bm = blockIdx.y * BM;
    const int bn = blockIdx.x * BN;
    const int tid = threadIdx.x;

    const int tm = (tid / 16) * TM;   // 0..120
    const int tn = (tid % 16) * TN;   // 0..120

    // Load mapping: A tile is 128 rows x 8 cols = 256 float4 (one per thread)
    const int aRow  = tid >> 1;        // 0..127
    const int aK4   = (tid & 1) * 4;   // 0 or 4
    // B tile is 8 rows x 128 cols = 256 float4 (one per thread)
    const int bRow  = tid >> 5;        // 0..7
    const int bCol4 = (tid & 31) * 4;  // 0..124

    const float* Aptr = A + (size_t)(bm + aRow) * K + aK4;
    const float* Bptr = B + (size_t)bRow * N + bn + bCol4;

    float acc[TM][TN];
#pragma unroll
    for (int i = 0; i < TM; i++)
#pragma unroll
        for (int j = 0; j < TN; j++) acc[i][j] = 0.f;

    for (int k0 = 0; k0 < K; k0 += BK) {
        float4 av = *(const float4*)Aptr;
        float4 bv = *(const float4*)Bptr;
        Aptr += BK;
        Bptr += (size_t)BK * N;

        As[aK4 + 0][aRow] = av.x;
        As[aK4 + 1][aRow] = av.y;
        As[aK4 + 2][aRow] = av.z;
        As[aK4 + 3][aRow] = av.w;
        *(float4*)&Bs[bRow][bCol4] = bv;
        __syncthreads();

#pragma unroll
        for (int kk = 0; kk < BK; kk++) {
            float ra[TM], rb[TN];
#pragma unroll
            for (int i = 0; i < TM; i++) ra[i] = As[kk][tm + i];
#pragma unroll
            for (int j = 0; j < TN; j++) rb[j] = Bs[kk][tn + j];
#pragma unroll
            for (int i = 0; i < TM; i++)
#pragma unroll
                for (int j = 0; j < TN; j++) acc[i][j] += ra[i] * rb[j];
        }
        __syncthreads();
    }

    // Epilogue: add bias, float4 stores
#pragma unroll
    for (int i = 0; i < TM; i++) {
        float* Crow = C + (size_t)(bm + tm + i) * N + bn + tn;
#pragma unroll
        for (int j = 0; j < TN; j += 4) {
            float4 v;
            v.x = acc[i][j + 0] + bias[bn + tn + j + 0];
            v.y = acc[i][j + 1] + bias[bn + tn + j + 1];
            v.z = acc[i][j + 2] + bias[bn + tn + j + 2];
            v.w = acc[i][j + 3] + bias[bn + tn + j + 3];
            *(float4*)(Crow + j) = v;
        }
    }
}

// ---------------------------------------------------------------------------
// BRC scan: one thread per (b, h) element; sequential over S.
//   a = 1 + tanh(xa + wa*h)
//   c = sigmoid(xc + wc*h)
//   h = c*h + (1-c)*tanh(xh + a*h)
// Writes y[s,b,h] every step and h_last at the end.
// ---------------------------------------------------------------------------
__global__ __launch_bounds__(256)
void brc_scan(const float* __restrict__ xa, const float* __restrict__ xc,
              const float* __restrict__ xh, const float* __restrict__ h0,
              const float* __restrict__ wa, const float* __restrict__ wc,
              float* __restrict__ y, float* __restrict__ h_last)
{
    const int idx = blockIdx.x * blockDim.x + threadIdx.x;  // 0 .. B*H-1
    const int hi = idx & (H_ - 1);

    float h = h0[idx];
    const float wav = wa[hi];
    const float wcv = wc[hi];

    size_t off = idx;
    const size_t stride = (size_t)B_ * H_;
#pragma unroll 4
    for (int s = 0; s < S_; s++) {
        const float va = xa[off];
        const float vc = xc[off];
        const float vh = xh[off];
        const float a = 1.f + tanhf(va + wav * h);
        const float c = 1.f / (1.f + expf(-(vc + wcv * h)));
        h = c * h + (1.f - c) * tanhf(vh + a * h);
        y[off] = h;
        off += stride;
    }
    h_last[idx] = h;
}

// ---------------------------------------------------------------------------
// Launch
// ---------------------------------------------------------------------------
extern "C" void kernel_launch(void* const* d_in, const int* in_sizes, int n_in,
                              void* d_out, int out_size)
{
    const float* x    = (const float*)d_in[0];
    const float* h0   = (const float*)d_in[1];
    const float* Ua0  = (const float*)d_in[2];
    const float* Uc0  = (const float*)d_in[3];
    const float* Uh0  = (const float*)d_in[4];
    const float* wa0  = (const float*)d_in[5];
    const float* wc0  = (const float*)d_in[6];
    const float* ba0  = (const float*)d_in[7];
    const float* bc0  = (const float*)d_in[8];
    const float* bh0  = (const float*)d_in[9];
    const float* Ua1  = (const float*)d_in[10];
    const float* Uc1  = (const float*)d_in[11];
    const float* Uh1  = (const float*)d_in[12];
    const float* wa1  = (const float*)d_in[13];
    const float* wc1  = (const float*)d_in[14];
    const float* ba1  = (const float*)d_in[15];
    const float* bc1  = (const float*)d_in[16];
    const float* bh1  = (const float*)d_in[17];
    const float* Wdec = (const float*)d_in[18];
    const float* bdec = (const float*)d_in[19];

    float* out    = (float*)d_out;                         // [S,B,OUT]
    float* hidden = out + (size_t)S_ * B_ * OUT_;          // [L,B,H]

    float *xa, *xc, *xh, *y;
    cudaGetSymbolAddress((void**)&xa, g_xa);
    cudaGetSymbolAddress((void**)&xc, g_xc);
    cudaGetSymbolAddress((void**)&xh, g_xh);
    cudaGetSymbolAddress((void**)&y,  g_y);

    const dim3 gridH(H_ / 128, MB_ / 128);    // N=1024 projections
    const dim3 gridO(OUT_ / 128, MB_ / 128);  // N=512 decoder
    const dim3 blk(256);
    const dim3 scanGrid((B_ * H_) / 256);

    // Layer 0 projections: x [32768,512] @ U [512,1024]
    sgemm_bias<<<gridH, blk>>>(x, Ua0, ba0, xa, MB_, H_, IN_);
    sgemm_bias<<<gridH, blk>>>(x, Uc0, bc0, xc, MB_, H_, IN_);
    sgemm_bias<<<gridH, blk>>>(x, Uh0, bh0, xh, MB_, H_, IN_);

    // Layer 0 scan -> y0 (in g_y), h_last -> hidden[0]
    brc_scan<<<scanGrid, blk>>>(xa, xc, xh, h0, wa0, wc0, y, hidden);

    // Layer 1 projections: y0 [32768,1024] @ U [1024,1024] (reuse proj buffers)
    sgemm_bias<<<gridH, blk>>>(y, Ua1, ba1, xa, MB_, H_, H_);
    sgemm_bias<<<gridH, blk>>>(y, Uc1, bc1, xc, MB_, H_, H_);
    sgemm_bias<<<gridH, blk>>>(y, Uh1, bh1, xh, MB_, H_, H_);

    // Layer 1 scan -> y1 (overwrites g_y), h_last -> hidden[1]
    brc_scan<<<scanGrid, blk>>>(xa, xc, xh, h0 + (size_t)B_ * H_, wa1, wc1,
                                y, hidden + (size_t)B_ * H_);

    // Decoder: y1 [32768,1024] @ Wdec [1024,512] + bdec -> out
    sgemm_bias<<<gridO, blk>>>(y, Wdec, bdec, out, MB_, OUT_, H_);
}

// round 2
// speedup vs baseline: 1.0002x; 1.0002x over previous
#include <cuda_runtime.h>
#include <math.h>

// Problem dims (fixed by the dataset)
#define S_  512
#define B_  64
#define IN_ 512
#define H_  1024
#define OUT_ 512
#define MB_ (S_ * B_)          // 32768 rows for all time-parallel GEMMs

// ---------------------------------------------------------------------------
// Scratch (no cudaMalloc allowed): 4 buffers of S*B*H floats = 4 * 134 MB
// ---------------------------------------------------------------------------
__device__ float g_xa[(size_t)S_ * B_ * H_];
__device__ float g_xc[(size_t)S_ * B_ * H_];
__device__ float g_xh[(size_t)S_ * B_ * H_];
__device__ float g_y [(size_t)S_ * B_ * H_];

// ---------------------------------------------------------------------------
// SGEMM: C[M,N] = A[M,K] @ B[K,N] + bias[N]
// 128x128 block tile, K-tile 8, 256 threads, 8x8 register tile per thread.
// All dims here are multiples of the tiles (M=32768, N in {512,1024},
// K in {512,1024}) so no boundary guards.
// ---------------------------------------------------------------------------
__global__ __launch_bounds__(256, 2)
void sgemm_bias(const float* __restrict__ A, const float* __restrict__ B,
                const float* __restrict__ bias, float* __restrict__ C,
                int M, int N, int K)
{
    const int BM = 128, BN = 128, BK = 8, TM = 8, TN = 8;
    __shared__ float As[BK][BM];
    __shared__ float Bs[BK][BN];

    const int bm = blockIdx.y * BM;
    const int bn = blockIdx.x * BN;
    const int tid = threadIdx.x;

    const int tm = (tid / 16) * TM;   // 0..120
    const int tn = (tid % 16) * TN;   // 0..120

    // Load mapping: A tile is 128 rows x 8 cols = 256 float4 (one per thread)
    const int aRow  = tid >> 1;        // 0..127
    const int aK4   = (tid & 1) * 4;   // 0 or 4
    // B tile is 8 rows x 128 cols = 256 float4 (one per thread)
    const int bRow  = tid >> 5;        // 0..7
    const int bCol4 = (tid & 31) * 4;  // 0..124

    const float* Aptr = A + (size_t)(bm + aRow) * K + aK4;
    const float* Bptr = B + (size_t)bRow * N + bn + bCol4;

    float acc[TM][TN];
#pragma unroll
    for (int i = 0; i < TM; i++)
#pragma unroll
        for (int j = 0; j < TN; j++) acc[i][j] = 0.f;

    for (int k0 = 0; k0 < K; k0 += BK) {
        float4 av = *(const float4*)Aptr;
        float4 bv = *(const float4*)Bptr;
        Aptr += BK;
        Bptr += (size_t)BK * N;

        As[aK4 + 0][aRow] = av.x;
        As[aK4 + 1][aRow] = av.y;
        As[aK4 + 2][aRow] = av.z;
        As[aK4 + 3][aRow] = av.w;
        *(float4*)&Bs[bRow][bCol4] = bv;
        __syncthreads();

#pragma unroll
        for (int kk = 0; kk < BK; kk++) {
            float ra[TM], rb[TN];
#pragma unroll
            for (int i = 0; i < TM; i++) ra[i] = As[kk][tm + i];
#pragma unroll
            for (int j = 0; j < TN; j++) rb[j] = Bs[kk][tn + j];
#pragma unroll
            for (int i = 0; i < TM; i++)
#pragma unroll
                for (int j = 0; j < TN; j++) acc[i][j] += ra[i] * rb[j];
        }
        __syncthreads();
    }

    // Epilogue: add bias, float4 stores
#pragma unroll
    for (int i = 0; i < TM; i++) {
        float* Crow = C + (size_t)(bm + tm + i) * N + bn + tn;
#pragma unroll
        for (int j = 0; j < TN; j += 4) {
            float4 v;
            v.x = acc[i][j + 0] + bias[bn + tn + j + 0];
            v.y = acc[i][j + 1] + bias[bn + tn + j + 1];
            v.z = acc[i][j + 2] + bias[bn + tn + j + 2];
            v.w = acc[i][j + 3] + bias[bn + tn + j + 3];
            *(float4*)(Crow + j) = v;
        }
    }
}

// ---------------------------------------------------------------------------
// BRC scan: one thread per (b, h) element; sequential over S.
//   a = 1 + tanh(xa + wa*h)
//   c = sigmoid(xc + wc*h)
//   h = c*h + (1-c)*tanh(xh + a*h)
// Writes y[s,b,h] every step and h_last at the end.
// ---------------------------------------------------------------------------
__global__ __launch_bounds__(256)
void brc_scan(const float* __restrict__ xa, const float* __restrict__ xc,
              const float* __restrict__ xh, const float* __restrict__ h0,
              const float* __restrict__ wa, const float* __restrict__ wc,
              float* __restrict__ y, float* __restrict__ h_last)
{
    const int idx = blockIdx.x * blockDim.x + threadIdx.x;  // 0 .. B*H-1
    const int hi = idx & (H_ - 1);

    float h = h0[idx];
    const float wav = wa[hi];
    const float wcv = wc[hi];

    size_t off = idx;
    const size_t stride = (size_t)B_ * H_;
#pragma unroll 4
    for (int s = 0; s < S_; s++) {
        const float va = xa[off];
        const float vc = xc[off];
        const float vh = xh[off];
        const float a = 1.f + tanhf(va + wav * h);
        const float c = 1.f / (1.f + expf(-(vc + wcv * h)));
        h = c * h + (1.f - c) * tanhf(vh + a * h);
        y[off] = h;
        off += stride;
    }
    h_last[idx] = h;
}

// ---------------------------------------------------------------------------
// Launch
// ---------------------------------------------------------------------------
extern "C" void kernel_launch(void* const* d_in, const int* in_sizes, int n_in,
                              void* d_out, int out_size)
{
    const float* x    = (const float*)d_in[0];
    const float* h0   = (const float*)d_in[1];
    const float* Ua0  = (const float*)d_in[2];
    const float* Uc0  = (const float*)d_in[3];
    const float* Uh0  = (const float*)d_in[4];
    const float* wa0  = (const float*)d_in[5];
    const float* wc0  = (const float*)d_in[6];
    const float* ba0  = (const float*)d_in[7];
    const float* bc0  = (const float*)d_in[8];
    const float* bh0  = (const float*)d_in[9];
    const float* Ua1  = (const float*)d_in[10];
    const float* Uc1  = (const float*)d_in[11];
    const float* Uh1  = (const float*)d_in[12];
    const float* wa1  = (const float*)d_in[13];
    const float* wc1  = (const float*)d_in[14];
    const float* ba1  = (const float*)d_in[15];
    const float* bc1  = (const float*)d_in[16];
    const float* bh1  = (const float*)d_in[17];
    const float* Wdec = (const float*)d_in[18];
    const float* bdec = (const float*)d_in[19];

    float* out    = (float*)d_out;                         // [S,B,OUT]
    float* hidden = out + (size_t)S_ * B_ * OUT_;          // [L,B,H]

    float *xa, *xc, *xh, *y;
    cudaGetSymbolAddress((void**)&xa, g_xa);
    cudaGetSymbolAddress((void**)&xc, g_xc);
    cudaGetSymbolAddress((void**)&xh, g_xh);
    cudaGetSymbolAddress((void**)&y,  g_y);

    const dim3 gridH(H_ / 128, MB_ / 128);    // N=1024 projections
    const dim3 gridO(OUT_ / 128, MB_ / 128);  // N=512 decoder
    const dim3 blk(256);
    const dim3 scanGrid((B_ * H_) / 256);

    // Layer 0 projections: x [32768,512] @ U [512,1024]
    sgemm_bias<<<gridH, blk>>>(x, Ua0, ba0, xa, MB_, H_, IN_);
    sgemm_bias<<<gridH, blk>>>(x, Uc0, bc0, xc, MB_, H_, IN_);
    sgemm_bias<<<gridH, blk>>>(x, Uh0, bh0, xh, MB_, H_, IN_);

    // Layer 0 scan -> y0 (in g_y), h_last -> hidden[0]
    brc_scan<<<scanGrid, blk>>>(xa, xc, xh, h0, wa0, wc0, y, hidden);

    // Layer 1 projections: y0 [32768,1024] @ U [1024,1024] (reuse proj buffers)
    sgemm_bias<<<gridH, blk>>>(y, Ua1, ba1, xa, MB_, H_, H_);
    sgemm_bias<<<gridH, blk>>>(y, Uc1, bc1, xc, MB_, H_, H_);
    sgemm_bias<<<gridH, blk>>>(y, Uh1, bh1, xh, MB_, H_, H_);

    // Layer 1 scan -> y1 (overwrites g_y), h_last -> hidden[1]
    brc_scan<<<scanGrid, blk>>>(xa, xc, xh, h0 + (size_t)B_ * H_, wa1, wc1,
                                y, hidden + (size_t)B_ * H_);

    // Decoder: y1 [32768,1024] @ Wdec [1024,512] + bdec -> out
    sgemm_bias<<<gridO, blk>>>(y, Wdec, bdec, out, MB_, OUT_, H_);
}

// round 4
// speedup vs baseline: 3.8875x; 3.8869x over previous
#include <cuda_runtime.h>
#include <math.h>
#include <stdint.h>

// Problem dims (fixed)
#define S_   512
#define B_   64
#define IN_  512
#define H_   1024
#define OUT_ 512
#define MB_  (S_ * B_)   // 32768 rows in all time-parallel GEMMs
#define H3_  (3 * H_)    // 3072 fused projection columns

// ---------------------------------------------------------------------------
// Scratch (__device__ globals; no cudaMalloc allowed)
// ---------------------------------------------------------------------------
__device__ float g_proj[(size_t)MB_ * H3_];   // fused xa|xc|xh  (384 MB)
__device__ float g_y   [(size_t)MB_ * H_];    // layer outputs (tf32-rounded)
__device__ float g_xt  [(size_t)MB_ * IN_];   // x converted to tf32
__device__ float g_bt0 [(size_t)H3_ * IN_];   // [3H][IN]  transposed L0 weights (tf32)
__device__ float g_bt1 [(size_t)H3_ * H_];    // [3H][H]   transposed L1 weights (tf32)
__device__ float g_btd [(size_t)OUT_ * H_];   // [OUT][H]  transposed decoder   (tf32)
__device__ float g_bias0[H3_];
__device__ float g_bias1[H3_];

// ---------------------------------------------------------------------------
// Inline PTX (sm_80-compatible only: cp.async + mma.sync tf32)
// ---------------------------------------------------------------------------
__device__ __forceinline__ uint32_t smem_u32(const void* p) {
    uint32_t a;
    asm("{ .reg .u64 t; cvta.to.shared.u64 t, %1; cvt.u32.u64 %0, t; }" : "=r"(a) : "l"(p));
    return a;
}
#define CP_ASYNC16(dst, src) \
    asm volatile("cp.async.cg.shared.global [%0], [%1], 16;" :: "r"(dst), "l"(src) : "memory")
#define CP_COMMIT() asm volatile("cp.async.commit_group;" ::: "memory")
#define CP_WAIT(n)  asm volatile("cp.async.wait_group %0;" :: "n"(n) : "memory")

__device__ __forceinline__ uint32_t lds32(uint32_t a) {
    uint32_t v;
    asm volatile("ld.shared.b32 %0, [%1];" : "=r"(v) : "r"(a));
    return v;
}
__device__ __forceinline__ uint32_t f2tf32(float x) {
    uint32_t r;
    asm("cvt.rna.tf32.f32 %0, %1;" : "=r"(r) : "f"(x));
    return r;
}
__device__ __forceinline__ void mma_tf32(float* d, const uint32_t* a, const uint32_t* b) {
    asm volatile(
        "mma.sync.aligned.m16n8k8.row.col.f32.tf32.tf32.f32 "
        "{%0,%1,%2,%3}, {%4,%5,%6,%7}, {%8,%9}, {%0,%1,%2,%3};"
        : "+f"(d[0]), "+f"(d[1]), "+f"(d[2]), "+f"(d[3])
        : "r"(a[0]), "r"(a[1]), "r"(a[2]), "r"(a[3]), "r"(b[0]), "r"(b[1]));
}

// ---------------------------------------------------------------------------
// TF32 tensor-core GEMM: C[M,N] = A[M,K] @ Bt[N,K]^T + bias[N]
// A, Bt must already hold tf32-rounded fp32 bit patterns.
// 128x128 block tile, BK=32, 256 threads (8 warps, 64x32 warp tile),
// 4-stage cp.async pipeline. M,N,K multiples of tiles; no guards.
// Smem per stage: A 16KB + B 16KB. Chunk-XOR swizzle: 16B chunk c of row r
// stored at chunk c ^ (r&7)  -> all fragment LDS.32 are conflict-free.
// ---------------------------------------------------------------------------
#define STAGES 4
#define STAGE_BYTES 32768
#define GEMM_SMEM (STAGES * STAGE_BYTES)

__device__ __forceinline__ void stage_load(const float* __restrict__ A,
                                           const float* __restrict__ Bt,
                                           int K, uint32_t stage_base,
                                           int bm, int bn, int k0, int tid) {
#pragma unroll
    for (int i = 0; i < 4; i++) {                 // A: 128 rows x 8 chunks
        int q = tid + i * 256;
        int r = q >> 3, c = q & 7;
        const float* g = A + (size_t)(bm + r) * K + k0 + c * 4;
        CP_ASYNC16(stage_base + (uint32_t)(r * 128 + ((c ^ (r & 7)) * 16)), g);
    }
#pragma unroll
    for (int i = 0; i < 4; i++) {                 // B: 128 rows x 8 chunks
        int q = tid + i * 256;
        int r = q >> 3, c = q & 7;
        const float* g = Bt + (size_t)(bn + r) * K + k0 + c * 4;
        CP_ASYNC16(stage_base + 16384u + (uint32_t)(r * 128 + ((c ^ (r & 7)) * 16)), g);
    }
}

__global__ __launch_bounds__(256)
void gemm_tf32(const float* __restrict__ A, const float* __restrict__ Bt,
               const float* __restrict__ bias, float* __restrict__ C,
               int N, int K)
{
    extern __shared__ char smraw[];
    const uint32_t smbase = smem_u32(smraw);

    const int tid  = threadIdx.x;
    const int w    = tid >> 5, lane = tid & 31;
    const int wm   = (w >> 2) * 64;      // warp m-offset (0/64)
    const int wn   = (w & 3) * 32;       // warp n-offset (0/32/64/96)
    const int bm   = blockIdx.y * 128;
    const int bn   = blockIdx.x * 128;
    const int nkt  = K / 32;
    const int r0   = lane >> 2;          // 0..7
    const int c0   = lane & 3;           // 0..3

    float acc[4][4][4];
#pragma unroll
    for (int mi = 0; mi < 4; mi++)
#pragma unroll
        for (int ni = 0; ni < 4; ni++)
#pragma unroll
            for (int j = 0; j < 4; j++) acc[mi][ni][j] = 0.f;

    // prologue: 3 stages in flight
#pragma unroll
    for (int t = 0; t < STAGES - 1; t++) {
        stage_load(A, Bt, K, smbase + (uint32_t)t * STAGE_BYTES, bm, bn, t * 32, tid);
        CP_COMMIT();
    }

    for (int t = 0; t < nkt; t++) {
        const int s = t & 3;
        CP_WAIT(2);
        __syncthreads();

        // issue loads for tile t+3 into stage (t+3)&3 == (t-1)&3 (safe: computed
        // at iter t-1, protected by the syncthreads above)
        if (t + STAGES - 1 < nkt)
            stage_load(A, Bt, K, smbase + (uint32_t)((t + 3) & 3) * STAGE_BYTES,
                       bm, bn, (t + 3) * 32, tid);
        CP_COMMIT();

        const uint32_t abase = smbase + (uint32_t)s * STAGE_BYTES;
        const uint32_t bbase = abase + 16384u;

#pragma unroll
        for (int ks = 0; ks < 4; ks++) {
            uint32_t afr[4][4], bfr[4][2];
#pragma unroll
            for (int mi = 0; mi < 4; mi++) {
                const int ra = wm + mi * 16 + r0;       // (ra+8)&7 == ra&7
                const uint32_t rb = abase + (uint32_t)ra * 128 + (uint32_t)c0 * 4;
                const uint32_t ch0 = (uint32_t)((2 * ks) ^ (ra & 7)) * 16;
                const uint32_t ch1 = (uint32_t)((2 * ks + 1) ^ (ra & 7)) * 16;
                afr[mi][0] = lds32(rb + ch0);
                afr[mi][1] = lds32(rb + 8 * 128 + ch0);
                afr[mi][2] = lds32(rb + ch1);
                afr[mi][3] = lds32(rb + 8 * 128 + ch1);
            }
#pragma unroll
            for (int ni = 0; ni < 4; ni++) {
                const int rn = wn + ni * 8 + r0;
                const uint32_t rb = bbase + (uint32_t)rn * 128 + (uint32_t)c0 * 4;
                bfr[ni][0] = lds32(rb + (uint32_t)((2 * ks) ^ (rn & 7)) * 16);
                bfr[ni][1] = lds32(rb + (uint32_t)((2 * ks + 1) ^ (rn & 7)) * 16);
            }
#pragma unroll
            for (int mi = 0; mi < 4; mi++)
#pragma unroll
                for (int ni = 0; ni < 4; ni++)
                    mma_tf32(acc[mi][ni], afr[mi], bfr[ni]);
        }
    }

    // epilogue: d0,d1 at (row, col..col+1), d2,d3 at (row+8, ...)
#pragma unroll
    for (int mi = 0; mi < 4; mi++) {
        const int row = bm + wm + mi * 16 + r0;
#pragma unroll
        for (int ni = 0; ni < 4; ni++) {
            const int col = bn + wn + ni * 8 + c0 * 2;
            const float b0 = bias[col], b1 = bias[col + 1];
            float2 v0 = make_float2(acc[mi][ni][0] + b0, acc[mi][ni][1] + b1);
            float2 v1 = make_float2(acc[mi][ni][2] + b0, acc[mi][ni][3] + b1);
            *(float2*)(C + (size_t)row * N + col) = v0;
            *(float2*)(C + (size_t)(row + 8) * N + col) = v1;
        }
    }
}

// ---------------------------------------------------------------------------
// Tiled transpose + tf32 rounding: out[c][r] = tf32(in[r][c])
// ---------------------------------------------------------------------------
__global__ void transpose32(const float* __restrict__ in, float* __restrict__ out,
                            int R, int C)
{
    __shared__ float t[32][33];
    int r0 = blockIdx.y * 32, c0 = blockIdx.x * 32;
    int tx = threadIdx.x, ty = threadIdx.y;
#pragma unroll
    for (int i = 0; i < 32; i += 8)
        t[ty + i][tx] = in[(size_t)(r0 + ty + i) * C + c0 + tx];
    __syncthreads();
#pragma unroll
    for (int i = 0; i < 32; i += 8)
        out[(size_t)(c0 + ty + i) * R + r0 + tx] =
            __uint_as_float(f2tf32(t[tx][ty + i]));
}

// elementwise tf32 rounding (float4), n divisible by 1024
__global__ void cvt_tf32(const float* __restrict__ in, float* __restrict__ out)
{
    size_t i = ((size_t)blockIdx.x * 256 + threadIdx.x) * 4;
    float4 v = *(const float4*)(in + i);
    v.x = __uint_as_float(f2tf32(v.x));
    v.y = __uint_as_float(f2tf32(v.y));
    v.z = __uint_as_float(f2tf32(v.z));
    v.w = __uint_as_float(f2tf32(v.w));
    *(float4*)(out + i) = v;
}

__global__ void bias_concat(const float* a, const float* c, const float* h,
                            float* out)
{
    int i = blockIdx.x * 256 + threadIdx.x;   // 0..3H-1
    const float* src = (i < H_) ? a : (i < 2 * H_) ? c : h;
    out[i] = src[i & (H_ - 1)];
}

// ---------------------------------------------------------------------------
// BRC scan with 8-deep prefetch ring. proj row layout [S,B,3H]: xa|xc|xh.
// y is written tf32-rounded (it only feeds downstream GEMMs); h stays fp32.
// ---------------------------------------------------------------------------
__global__ __launch_bounds__(128)
void brc_scan(const float* __restrict__ proj, const float* __restrict__ h0,
              const float* __restrict__ wa, const float* __restrict__ wc,
              float* __restrict__ y, float* __restrict__ h_last)
{
    const int idx = blockIdx.x * 128 + threadIdx.x;   // b*H + h
    const int b  = idx >> 10;
    const int hi = idx & (H_ - 1);

    float h = h0[idx];
    const float wav = wa[hi];
    const float wcv = wc[hi];

    const size_t pbase   = (size_t)b * H3_ + hi;
    const size_t pstride = (size_t)B_ * H3_;
    const size_t ystride = (size_t)B_ * H_;

    float bufa[8], bufc[8], bufh[8];
#pragma unroll
    for (int j = 0; j < 8; j++) {
        size_t o = pbase + (size_t)j * pstride;
        bufa[j] = proj[o]; bufc[j] = proj[o + H_]; bufh[j] = proj[o + 2 * H_];
    }

    size_t yoff = idx;
    for (int so = 0; so < S_; so += 8) {
        const bool pf = (so + 8 < S_);
#pragma unroll
        for (int j = 0; j < 8; j++) {
            float va = bufa[j], vc = bufc[j], vh = bufh[j];
            if (pf) {
                size_t o = pbase + (size_t)(so + j + 8) * pstride;
                bufa[j] = proj[o]; bufc[j] = proj[o + H_]; bufh[j] = proj[o + 2 * H_];
            }
            float a = 1.f + tanhf(va + wav * h);
            float c = 1.f / (1.f + expf(-(vc + wcv * h)));
            h = c * h + (1.f - c) * tanhf(vh + a * h);
            y[yoff] = __uint_as_float(f2tf32(h));
            yoff += ystride;
        }
    }
    h_last[idx] = h;
}

// ---------------------------------------------------------------------------
// Launch
// ---------------------------------------------------------------------------
extern "C" void kernel_launch(void* const* d_in, const int* in_sizes, int n_in,
                              void* d_out, int out_size)
{
    const float* x    = (const float*)d_in[0];
    const float* h0   = (const float*)d_in[1];
    const float* Ua0  = (const float*)d_in[2];
    const float* Uc0  = (const float*)d_in[3];
    const float* Uh0  = (const float*)d_in[4];
    const float* wa0  = (const float*)d_in[5];
    const float* wc0  = (const float*)d_in[6];
    const float* ba0  = (const float*)d_in[7];
    const float* bc0  = (const float*)d_in[8];
    const float* bh0  = (const float*)d_in[9];
    const float* Ua1  = (const float*)d_in[10];
    const float* Uc1  = (const float*)d_in[11];
    const float* Uh1  = (const float*)d_in[12];
    const float* wa1  = (const float*)d_in[13];
    const float* wc1  = (const float*)d_in[14];
    const float* ba1  = (const float*)d_in[15];
    const float* bc1  = (const float*)d_in[16];
    const float* bh1  = (const float*)d_in[17];
    const float* Wdec = (const float*)d_in[18];
    const float* bdec = (const float*)d_in[19];

    float* out    = (float*)d_out;
    float* hidden = out + (size_t)S_ * B_ * OUT_;

    float *proj, *y, *xt, *bt0, *bt1, *btd, *bias0, *bias1;
    cudaGetSymbolAddress((void**)&proj,  g_proj);
    cudaGetSymbolAddress((void**)&y,     g_y);
    cudaGetSymbolAddress((void**)&xt,    g_xt);
    cudaGetSymbolAddress((void**)&bt0,   g_bt0);
    cudaGetSymbolAddress((void**)&bt1,   g_bt1);
    cudaGetSymbolAddress((void**)&btd,   g_btd);
    cudaGetSymbolAddress((void**)&bias0, g_bias0);
    cudaGetSymbolAddress((void**)&bias1, g_bias1);

    cudaFuncSetAttribute(gemm_tf32, cudaFuncAttributeMaxDynamicSharedMemorySize,
                         GEMM_SMEM);

    const dim3 tblk(32, 8);
    // L0 weights [IN,H] -> [H,IN] slabs (tf32-rounded)
    transpose32<<<dim3(H_ / 32, IN_ / 32), tblk>>>(Ua0, bt0 + 0 * (size_t)H_ * IN_, IN_, H_);
    transpose32<<<dim3(H_ / 32, IN_ / 32), tblk>>>(Uc0, bt0 + 1 * (size_t)H_ * IN_, IN_, H_);
    transpose32<<<dim3(H_ / 32, IN_ / 32), tblk>>>(Uh0, bt0 + 2 * (size_t)H_ * IN_, IN_, H_);
    // L1 weights [H,H] -> [H,H]
    transpose32<<<dim3(H_ / 32, H_ / 32), tblk>>>(Ua1, bt1 + 0 * (size_t)H_ * H_, H_, H_);
    transpose32<<<dim3(H_ / 32, H_ / 32), tblk>>>(Uc1, bt1 + 1 * (size_t)H_ * H_, H_, H_);
    transpose32<<<dim3(H_ / 32, H_ / 32), tblk>>>(Uh1, bt1 + 2 * (size_t)H_ * H_, H_, H_);
    // Wdec [H,OUT] -> [OUT,H]
    transpose32<<<dim3(OUT_ / 32, H_ / 32), tblk>>>(Wdec, btd, H_, OUT_);

    bias_concat<<<H3_ / 256, 256>>>(ba0, bc0, bh0, bias0);
    bias_concat<<<H3_ / 256, 256>>>(ba1, bc1, bh1, bias1);

    // x -> tf32
    cvt_tf32<<<(MB_ * IN_) / 1024, 256>>>(x, xt);

    const dim3 gblk(256);
    const dim3 scanGrid((B_ * H_) / 128), sblk(128);

    // Layer 0 fused projections: [32768,512] @ [512,3072]
    gemm_tf32<<<dim3(H3_ / 128, MB_ / 128), gblk, GEMM_SMEM>>>(xt, bt0, bias0, proj, H3_, IN_);
    brc_scan<<<scanGrid, sblk>>>(proj, h0, wa0, wc0, y, hidden);

    // Layer 1 fused projections: [32768,1024] @ [1024,3072]
    gemm_tf32<<<dim3(H3_ / 128, MB_ / 128), gblk, GEMM_SMEM>>>(y, bt1, bias1, proj, H3_, H_);
    brc_scan<<<scanGrid, sblk>>>(proj, h0 + (size_t)B_ * H_, wa1, wc1, y,
                                 hidden + (size_t)B_ * H_);

    // Decoder: [32768,1024] @ [1024,512]
    gemm_tf32<<<dim3(OUT_ / 128, MB_ / 128), gblk, GEMM_SMEM>>>(y, btd, bdec, out, OUT_, H_);
}